// round 1
// baseline (speedup 1.0000x reference)
#include <cuda_runtime.h>
#include <cstdint>

// ---------------- scratch (device globals; no allocation allowed) ----------
#define MAXN 20000
__device__ float g_H[(size_t)MAXN * 1280];   // GEMM output buffer
__device__ float g_A[(size_t)MAXN * 1280];   // aggregation buffer
__device__ float g_dis[MAXN];
__device__ int   g_deg[MAXN];
__device__ float g_pool[64 * 320];
__device__ float g_cnt[64];
__device__ float g_m1[64 * 1024];
__device__ float g_mc[64 * 193];
__device__ float g_m3[64 * 1024];
__device__ float g_m4[64 * 512];

// ---------------- small utility kernels ------------------------------------
__global__ void k_init_deg(int* deg, int n) {
    int i = blockIdx.x * blockDim.x + threadIdx.x;
    if (i < n) deg[i] = 1;                       // self-loop
}
__global__ void k_count_deg(const int* __restrict__ dst, int* deg, int e) {
    int i = blockIdx.x * blockDim.x + threadIdx.x;
    if (i < e) atomicAdd(&deg[dst[i]], 1);
}
__global__ void k_dis(const int* __restrict__ deg, float* dis, int n) {
    int i = blockIdx.x * blockDim.x + threadIdx.x;
    if (i < n) dis[i] = rsqrtf((float)deg[i]);
}
__global__ void k_zero(float* p, size_t n) {
    size_t i = (size_t)blockIdx.x * blockDim.x + threadIdx.x;
    if (i < n) p[i] = 0.0f;
}

// ---------------- fp32 tiled GEMM: C[N,M] = A[N,K] @ B[K,M] ----------------
// BM=128, BN=64, BK=16, 256 threads, 8x4 per-thread microtile.
// Requires K % 16 == 0, M % 64 == 0 (true for all large GEMMs here).
__global__ void __launch_bounds__(256)
k_gemm(const float* __restrict__ A, const float* __restrict__ B,
       float* __restrict__ C, int N, int K, int M) {
    __shared__ float As[16][128];
    __shared__ float Bs[16][64];
    const int row0 = blockIdx.y * 128;
    const int col0 = blockIdx.x * 64;
    const int tid = threadIdx.x;
    const int tx = tid & 15;    // 16 col-groups of 4
    const int ty = tid >> 4;    // 16 row-groups of 8

    float acc[8][4];
#pragma unroll
    for (int i = 0; i < 8; i++)
#pragma unroll
        for (int j = 0; j < 4; j++) acc[i][j] = 0.0f;

    for (int k0 = 0; k0 < K; k0 += 16) {
        // load A tile (128x16) transposed: 512 float4, 2 per thread
#pragma unroll
        for (int l = 0; l < 2; l++) {
            int p = tid + l * 256;
            int r = p >> 2;
            int kc = (p & 3) * 4;
            int gr = row0 + r;
            float4 v = make_float4(0.f, 0.f, 0.f, 0.f);
            if (gr < N) v = *(const float4*)(A + (size_t)gr * K + k0 + kc);
            As[kc + 0][r] = v.x;
            As[kc + 1][r] = v.y;
            As[kc + 2][r] = v.z;
            As[kc + 3][r] = v.w;
        }
        // load B tile (16x64): 256 float4, 1 per thread
        {
            int kr = tid >> 4;
            int cc = (tid & 15) * 4;
            float4 v = *(const float4*)(B + (size_t)(k0 + kr) * M + col0 + cc);
            *(float4*)&Bs[kr][cc] = v;
        }
        __syncthreads();
#pragma unroll
        for (int kk = 0; kk < 16; kk++) {
            float a[8], b[4];
#pragma unroll
            for (int i = 0; i < 8; i++) a[i] = As[kk][ty * 8 + i];
#pragma unroll
            for (int j = 0; j < 4; j++) b[j] = Bs[kk][tx * 4 + j];
#pragma unroll
            for (int i = 0; i < 8; i++)
#pragma unroll
                for (int j = 0; j < 4; j++) acc[i][j] += a[i] * b[j];
        }
        __syncthreads();
    }
#pragma unroll
    for (int i = 0; i < 8; i++) {
        int gr = row0 + ty * 8 + i;
        if (gr < N) {
            float4 v = make_float4(acc[i][0], acc[i][1], acc[i][2], acc[i][3]);
            *(float4*)(C + (size_t)gr * M + col0 + tx * 4) = v;
        }
    }
}

// ---------------- edge scatter: A[dst] += H[src] * dis[src]*dis[dst] --------
__global__ void k_scatter(const float* __restrict__ H, float* __restrict__ A,
                          const int* __restrict__ src, const int* __restrict__ dst,
                          const float* __restrict__ dis, int M) {
    int e = blockIdx.x;
    int s = src[e], d = dst[e];
    float w = dis[s] * dis[d];
    const float* hs = H + (size_t)s * M;
    float* ad = A + (size_t)d * M;
    for (int f = threadIdx.x; f < M; f += blockDim.x)
        atomicAdd(&ad[f], hs[f] * w);
}

// ---------------- self-loop + bias + relu -----------------------------------
__global__ void k_sbr(const float* __restrict__ H, float* __restrict__ A,
                      const float* __restrict__ dis, const float* __restrict__ b,
                      int N, int M) {
    size_t idx = (size_t)blockIdx.x * blockDim.x + threadIdx.x;
    size_t tot = (size_t)N * M;
    if (idx >= tot) return;
    int i = (int)(idx / M);
    int f = (int)(idx % M);
    float di = dis[i];
    float v = A[idx] + H[idx] * di * di + b[f];
    A[idx] = v > 0.f ? v : 0.f;
}

// ---------------- pooling ----------------------------------------------------
__global__ void k_cntk(const int* __restrict__ batch, float* cnt, int N) {
    int i = blockIdx.x * blockDim.x + threadIdx.x;
    if (i < N) atomicAdd(&cnt[batch[i]], 1.0f);
}
__global__ void k_pool(const float* __restrict__ A, const int* __restrict__ batch,
                       float* pool, int N) {
    size_t idx = (size_t)blockIdx.x * blockDim.x + threadIdx.x;
    size_t tot = (size_t)N * 320;
    if (idx >= tot) return;
    int i = (int)(idx / 320);
    int f = (int)(idx % 320);
    atomicAdd(&pool[batch[i] * 320 + f], A[idx]);
}
__global__ void k_mean(float* pool, const float* __restrict__ cnt) {
    int idx = blockIdx.x * blockDim.x + threadIdx.x;
    if (idx < 64 * 320) pool[idx] /= fmaxf(cnt[idx / 320], 1.0f);
}

// ---------------- MLP head: out[g, off+m] = act(in[g,:] @ W[:,m] + b[m]) ----
__global__ void k_mlp(const float* __restrict__ in, const float* __restrict__ W,
                      const float* __restrict__ b, float* __restrict__ out,
                      int K, int M, int istride, int ostride, int ooff, int dorelu) {
    int g = blockIdx.y;
    int m = blockIdx.x * blockDim.x + threadIdx.x;
    if (m >= M) return;
    const float* ing = in + (size_t)g * istride;
    float acc = b[m];
    for (int k = 0; k < K; k++) acc += ing[k] * W[(size_t)k * M + m];
    if (dorelu) acc = fmaxf(acc, 0.0f);
    out[(size_t)g * ostride + ooff + m] = acc;
}

__global__ void k_copyfp(const float* __restrict__ fp, float* __restrict__ mc) {
    int idx = blockIdx.x * blockDim.x + threadIdx.x;
    if (idx < 64 * 65) {
        int g = idx / 65, j = idx % 65;
        mc[g * 193 + j] = fp[idx];
    }
}

__global__ void k_final(const float* __restrict__ in, const float* __restrict__ Wo,
                        const float* __restrict__ bo, float* __restrict__ out) {
    int g = blockIdx.x;
    float acc = 0.f;
    for (int k = threadIdx.x; k < 512; k += 32) acc += in[g * 512 + k] * Wo[k];
#pragma unroll
    for (int o = 16; o; o >>= 1) acc += __shfl_down_sync(0xFFFFFFFFu, acc, o);
    if (threadIdx.x == 0) out[g] = acc + bo[0];
}

// ---------------- launch -----------------------------------------------------
extern "C" void kernel_launch(void* const* d_in, const int* in_sizes, int n_in,
                              void* d_out, int out_size) {
    const float* x     = (const float*)d_in[0];
    const int*   ei    = (const int*)d_in[1];
    const int*   batch = (const int*)d_in[2];
    const float* fp_x  = (const float*)d_in[3];
    const float* W1 = (const float*)d_in[4];   const float* b1 = (const float*)d_in[5];
    const float* W2 = (const float*)d_in[6];   const float* b2 = (const float*)d_in[7];
    const float* W3 = (const float*)d_in[8];   const float* b3 = (const float*)d_in[9];
    const float* Wg1 = (const float*)d_in[10]; const float* bg1 = (const float*)d_in[11];
    const float* Wg2 = (const float*)d_in[12]; const float* bg2 = (const float*)d_in[13];
    const float* Wf1 = (const float*)d_in[14]; const float* bf1 = (const float*)d_in[15];
    const float* Wf2 = (const float*)d_in[16]; const float* bf2 = (const float*)d_in[17];
    const float* Wo  = (const float*)d_in[18]; const float* bo  = (const float*)d_in[19];

    const int N = in_sizes[0] / 1280;
    const int E = in_sizes[1] / 2;
    const int G = in_sizes[3] / 65;
    const int* srcp = ei;
    const int* dstp = ei + E;

    float *pH, *pA, *pdis, *ppool, *pcnt, *pm1, *pmc, *pm3, *pm4;
    int* pdeg;
    cudaGetSymbolAddress((void**)&pH, g_H);
    cudaGetSymbolAddress((void**)&pA, g_A);
    cudaGetSymbolAddress((void**)&pdis, g_dis);
    cudaGetSymbolAddress((void**)&pdeg, g_deg);
    cudaGetSymbolAddress((void**)&ppool, g_pool);
    cudaGetSymbolAddress((void**)&pcnt, g_cnt);
    cudaGetSymbolAddress((void**)&pm1, g_m1);
    cudaGetSymbolAddress((void**)&pmc, g_mc);
    cudaGetSymbolAddress((void**)&pm3, g_m3);
    cudaGetSymbolAddress((void**)&pm4, g_m4);

    // degree / normalization
    k_init_deg<<<(N + 255) / 256, 256>>>(pdeg, N);
    k_count_deg<<<(E + 255) / 256, 256>>>(dstp, pdeg, E);
    k_dis<<<(N + 255) / 256, 256>>>(pdeg, pdis, N);

    auto run_layer = [&](const float* in, const float* W, const float* b,
                         int K, int M) {
        dim3 gg(M / 64, (N + 127) / 128);
        k_gemm<<<gg, 256>>>(in, W, pH, N, K, M);
        size_t tot = (size_t)N * M;
        k_zero<<<(unsigned)((tot + 255) / 256), 256>>>(pA, tot);
        k_scatter<<<E, 128>>>(pH, pA, srcp, dstp, pdis, M);
        k_sbr<<<(unsigned)((tot + 255) / 256), 256>>>(pH, pA, pdis, b, N, M);
    };

    run_layer(x, W1, b1, 1280, 1280);   // layer 1: A <- relu(gcn(x))
    run_layer(pA, W2, b2, 1280, 640);   // layer 2
    run_layer(pA, W3, b3, 640, 320);    // layer 3

    // global mean pool
    k_zero<<<(64 * 320 + 255) / 256, 256>>>(ppool, 64 * 320);
    k_zero<<<1, 64>>>(pcnt, 64);
    k_cntk<<<(N + 255) / 256, 256>>>(batch, pcnt, N);
    {
        size_t tot = (size_t)N * 320;
        k_pool<<<(unsigned)((tot + 255) / 256), 256>>>(pA, batch, ppool, N);
    }
    k_mean<<<(64 * 320 + 255) / 256, 256>>>(ppool, pcnt);

    // MLP head
    {
        dim3 g1(1024 / 256, G);
        k_mlp<<<g1, 256>>>(ppool, Wg1, bg1, pm1, 320, 1024, 320, 1024, 0, 1);
        dim3 g2(1, G);
        k_mlp<<<g2, 128>>>(pm1, Wg2, bg2, pmc, 1024, 128, 1024, 193, 65, 0);
        k_copyfp<<<(64 * 65 + 255) / 256, 256>>>(fp_x, pmc);
        dim3 g3(1024 / 256, G);
        k_mlp<<<g3, 256>>>(pmc, Wf1, bf1, pm3, 193, 1024, 193, 1024, 0, 1);
        dim3 g4(512 / 256, G);
        k_mlp<<<g4, 256>>>(pm3, Wf2, bf2, pm4, 1024, 512, 1024, 512, 0, 1);
        k_final<<<G, 32>>>(pm4, Wo, bo, (float*)d_out);
    }
}

// round 4
// speedup vs baseline: 1.6421x; 1.6421x over previous
#include <cuda_runtime.h>
#include <cstdint>

// ===================== scratch (device globals; no allocation allowed) ======
#define MAXN 20000
__device__ float g_H[(size_t)MAXN * 1280];
__device__ float g_A[(size_t)MAXN * 1280];
__device__ float g_dis[MAXN];
__device__ int   g_deg[MAXN];
__device__ float g_pool[64 * 320];
__device__ float g_cnt[64];
__device__ float g_m1[64 * 1024];
__device__ float g_mc[64 * 193];
__device__ float g_m3[64 * 1024];
__device__ float g_m4[64 * 512];

// ===================== helpers =====================
__device__ __forceinline__ uint32_t f2tf32(float x) {
    uint32_t r;
    asm("cvt.rna.tf32.f32 %0, %1;" : "=r"(r) : "f"(x));
    return r;
}

__device__ __forceinline__ void mma_tf32(float* d, const uint32_t* a, const uint32_t* b) {
    asm volatile(
        "mma.sync.aligned.m16n8k8.row.col.f32.tf32.tf32.f32 "
        "{%0,%1,%2,%3}, {%4,%5,%6,%7}, {%8,%9}, {%0,%1,%2,%3};\n"
        : "+f"(d[0]), "+f"(d[1]), "+f"(d[2]), "+f"(d[3])
        : "r"(a[0]), "r"(a[1]), "r"(a[2]), "r"(a[3]), "r"(b[0]), "r"(b[1]));
}

// ===================== utility kernels =====================
__global__ void k_init_deg(int* deg, int n) {
    int i = blockIdx.x * blockDim.x + threadIdx.x;
    if (i < n) deg[i] = 1;
}
__global__ void k_count_deg(const int* __restrict__ dst, int* deg, int e) {
    int i = blockIdx.x * blockDim.x + threadIdx.x;
    if (i < e) atomicAdd(&deg[dst[i]], 1);
}
__global__ void k_dis(const int* __restrict__ deg, float* dis, int n) {
    int i = blockIdx.x * blockDim.x + threadIdx.x;
    if (i < n) dis[i] = rsqrtf((float)deg[i]);
}
__global__ void k_zero(float* p, size_t n) {
    size_t i = (size_t)blockIdx.x * blockDim.x + threadIdx.x;
    if (i < n) p[i] = 0.0f;
}

// ===================== tensor-core tf32 GEMM ================================
// C[N, M] = A[N, K] @ W[K, M]
// Block tile 128x128, BK=16, 256 threads (8 warps, 2x4), warp tile 64x32.
// A smem: [128][20] words (stride 20 -> conflict-free frag loads)
// B smem: [16][132] words (stride 132 -> conflict-free frag loads)
#define ASTRIDE 20
#define BSTRIDE 132

__global__ void __launch_bounds__(256, 2)
k_gemm_tc(const float* __restrict__ A, const float* __restrict__ W,
          float* __restrict__ C, int N, int K, int M) {
    __shared__ uint32_t As[2][128 * ASTRIDE];
    __shared__ uint32_t Bs[2][16 * BSTRIDE];

    const int tid = threadIdx.x;
    const int wid = tid >> 5;
    const int lid = tid & 31;
    const int g4  = lid >> 2;   // groupID 0..7
    const int tg  = lid & 3;    // thread-in-group 0..3
    const int wm  = wid >> 2;   // warp m index 0..1
    const int wn  = wid & 3;    // warp n index 0..3
    const int row0 = blockIdx.y * 128;
    const int col0 = blockIdx.x * 128;

    float acc[4][4][4];
#pragma unroll
    for (int i = 0; i < 4; i++)
#pragma unroll
        for (int j = 0; j < 4; j++)
#pragma unroll
            for (int k = 0; k < 4; k++) acc[i][j][k] = 0.0f;

    // load indices (2 float4 each for A and B per thread)
    const int ar  = tid >> 2;          // A row within tile for p = tid
    const int ac  = (tid & 3) * 4;     // A col
    const int br  = tid >> 5;          // B row within tile
    const int bc  = (tid & 31) * 4;    // B col

    const int nk = K >> 4;             // K / 16

    float4 va[2], vb[2];
    auto load_tile = [&](int c) {
#pragma unroll
        for (int i = 0; i < 2; i++) {
            int r = ar + i * 64;       // p = tid + 256*i -> row += 64
            int gr = row0 + r;
            va[i] = (gr < N) ? *(const float4*)(A + (size_t)gr * K + c * 16 + ac)
                             : make_float4(0.f, 0.f, 0.f, 0.f);
        }
#pragma unroll
        for (int i = 0; i < 2; i++) {
            int r = br + i * 8;        // p = tid + 256*i -> row += 8
            int gc = col0 + bc;
            vb[i] = (gc < M) ? *(const float4*)(W + (size_t)(c * 16 + r) * M + gc)
                             : make_float4(0.f, 0.f, 0.f, 0.f);
        }
    };
    auto store_tile = [&](int buf) {
#pragma unroll
        for (int i = 0; i < 2; i++) {
            int r = ar + i * 64;
            uint32_t* p = &As[buf][r * ASTRIDE + ac];
            asm volatile("st.shared.v4.b32 [%0], {%1,%2,%3,%4};" ::
                "l"(p), "r"(f2tf32(va[i].x)), "r"(f2tf32(va[i].y)),
                "r"(f2tf32(va[i].z)), "r"(f2tf32(va[i].w)) : "memory");
        }
#pragma unroll
        for (int i = 0; i < 2; i++) {
            int r = br + i * 8;
            uint32_t* p = &Bs[buf][r * BSTRIDE + bc];
            asm volatile("st.shared.v4.b32 [%0], {%1,%2,%3,%4};" ::
                "l"(p), "r"(f2tf32(vb[i].x)), "r"(f2tf32(vb[i].y)),
                "r"(f2tf32(vb[i].z)), "r"(f2tf32(vb[i].w)) : "memory");
        }
    };

    load_tile(0);
    store_tile(0);
    __syncthreads();

    for (int c = 0; c < nk; c++) {
        const int buf = c & 1;
        if (c + 1 < nk) load_tile(c + 1);

        // compute on buf
        const uint32_t* __restrict__ as = As[buf];
        const uint32_t* __restrict__ bs = Bs[buf];
#pragma unroll
        for (int s = 0; s < 2; s++) {
            uint32_t af[4][4], bf[4][2];
            const int kc = s * 8;
#pragma unroll
            for (int mi = 0; mi < 4; mi++) {
                int r = wm * 64 + mi * 16 + g4;
                af[mi][0] = as[r * ASTRIDE + kc + tg];
                af[mi][1] = as[(r + 8) * ASTRIDE + kc + tg];
                af[mi][2] = as[r * ASTRIDE + kc + tg + 4];
                af[mi][3] = as[(r + 8) * ASTRIDE + kc + tg + 4];
            }
#pragma unroll
            for (int nf = 0; nf < 4; nf++) {
                int cc = wn * 32 + nf * 8 + g4;
                bf[nf][0] = bs[(kc + tg) * BSTRIDE + cc];
                bf[nf][1] = bs[(kc + tg + 4) * BSTRIDE + cc];
            }
#pragma unroll
            for (int mi = 0; mi < 4; mi++)
#pragma unroll
                for (int nf = 0; nf < 4; nf++)
                    mma_tf32(acc[mi][nf], af[mi], bf[nf]);
        }

        if (c + 1 < nk) store_tile((c + 1) & 1);
        __syncthreads();
    }

    // epilogue
#pragma unroll
    for (int mi = 0; mi < 4; mi++) {
        int r0 = row0 + wm * 64 + mi * 16 + g4;
#pragma unroll
        for (int nf = 0; nf < 4; nf++) {
            int cc = col0 + wn * 32 + nf * 8 + tg * 2;
            if (cc < M) {
                if (r0 < N)
                    *(float2*)(C + (size_t)r0 * M + cc) =
                        make_float2(acc[mi][nf][0], acc[mi][nf][1]);
                if (r0 + 8 < N)
                    *(float2*)(C + (size_t)(r0 + 8) * M + cc) =
                        make_float2(acc[mi][nf][2], acc[mi][nf][3]);
            }
        }
    }
}

// ===================== edge scatter =====================
__global__ void k_scatter(const float* __restrict__ H, float* __restrict__ A,
                          const int* __restrict__ src, const int* __restrict__ dst,
                          const float* __restrict__ dis, int M) {
    int e = blockIdx.x;
    int s = src[e], d = dst[e];
    float w = dis[s] * dis[d];
    const float* hs = H + (size_t)s * M;
    float* ad = A + (size_t)d * M;
    for (int f = threadIdx.x; f < M; f += blockDim.x)
        atomicAdd(&ad[f], hs[f] * w);
}

__global__ void k_sbr(const float* __restrict__ H, float* __restrict__ A,
                      const float* __restrict__ dis, const float* __restrict__ b,
                      int N, int M) {
    size_t idx = (size_t)blockIdx.x * blockDim.x + threadIdx.x;
    size_t tot = (size_t)N * M;
    if (idx >= tot) return;
    int i = (int)(idx / M);
    int f = (int)(idx % M);
    float di = dis[i];
    float v = A[idx] + H[idx] * di * di + b[f];
    A[idx] = v > 0.f ? v : 0.f;
}

// ===================== pooling =====================
__global__ void k_cntk(const int* __restrict__ batch, float* cnt, int N) {
    int i = blockIdx.x * blockDim.x + threadIdx.x;
    if (i < N) atomicAdd(&cnt[batch[i]], 1.0f);
}
__global__ void k_pool(const float* __restrict__ A, const int* __restrict__ batch,
                       float* pool, int N) {
    size_t idx = (size_t)blockIdx.x * blockDim.x + threadIdx.x;
    size_t tot = (size_t)N * 320;
    if (idx >= tot) return;
    int i = (int)(idx / 320);
    int f = (int)(idx % 320);
    atomicAdd(&pool[batch[i] * 320 + f], A[idx]);
}
__global__ void k_mean(float* pool, const float* __restrict__ cnt) {
    int idx = blockIdx.x * blockDim.x + threadIdx.x;
    if (idx < 64 * 320) pool[idx] /= fmaxf(cnt[idx / 320], 1.0f);
}

// ===================== MLP head =====================
__global__ void k_mlp(const float* __restrict__ in, const float* __restrict__ W,
                      const float* __restrict__ b, float* __restrict__ out,
                      int K, int M, int istride, int ostride, int ooff, int dorelu) {
    int g = blockIdx.y;
    int m = blockIdx.x * blockDim.x + threadIdx.x;
    if (m >= M) return;
    const float* ing = in + (size_t)g * istride;
    float acc = b[m];
    for (int k = 0; k < K; k++) acc += ing[k] * W[(size_t)k * M + m];
    if (dorelu) acc = fmaxf(acc, 0.0f);
    out[(size_t)g * ostride + ooff + m] = acc;
}

__global__ void k_copyfp(const float* __restrict__ fp, float* __restrict__ mc) {
    int idx = blockIdx.x * blockDim.x + threadIdx.x;
    if (idx < 64 * 65) {
        int g = idx / 65, j = idx % 65;
        mc[g * 193 + j] = fp[idx];
    }
}

__global__ void k_final(const float* __restrict__ in, const float* __restrict__ Wo,
                        const float* __restrict__ bo, float* __restrict__ out) {
    int g = blockIdx.x;
    float acc = 0.f;
    for (int k = threadIdx.x; k < 512; k += 32) acc += in[g * 512 + k] * Wo[k];
#pragma unroll
    for (int o = 16; o; o >>= 1) acc += __shfl_down_sync(0xFFFFFFFFu, acc, o);
    if (threadIdx.x == 0) out[g] = acc + bo[0];
}

// ===================== launch =====================
extern "C" void kernel_launch(void* const* d_in, const int* in_sizes, int n_in,
                              void* d_out, int out_size) {
    const float* x     = (const float*)d_in[0];
    const int*   ei    = (const int*)d_in[1];
    const int*   batch = (const int*)d_in[2];
    const float* fp_x  = (const float*)d_in[3];
    const float* W1 = (const float*)d_in[4];   const float* b1 = (const float*)d_in[5];
    const float* W2 = (const float*)d_in[6];   const float* b2 = (const float*)d_in[7];
    const float* W3 = (const float*)d_in[8];   const float* b3 = (const float*)d_in[9];
    const float* Wg1 = (const float*)d_in[10]; const float* bg1 = (const float*)d_in[11];
    const float* Wg2 = (const float*)d_in[12]; const float* bg2 = (const float*)d_in[13];
    const float* Wf1 = (const float*)d_in[14]; const float* bf1 = (const float*)d_in[15];
    const float* Wf2 = (const float*)d_in[16]; const float* bf2 = (const float*)d_in[17];
    const float* Wo  = (const float*)d_in[18]; const float* bo  = (const float*)d_in[19];

    const int N = in_sizes[0] / 1280;
    const int E = in_sizes[1] / 2;
    const int G = in_sizes[3] / 65;
    const int* srcp = ei;
    const int* dstp = ei + E;

    float *pH, *pA, *pdis, *ppool, *pcnt, *pm1, *pmc, *pm3, *pm4;
    int* pdeg;
    cudaGetSymbolAddress((void**)&pH, g_H);
    cudaGetSymbolAddress((void**)&pA, g_A);
    cudaGetSymbolAddress((void**)&pdis, g_dis);
    cudaGetSymbolAddress((void**)&pdeg, g_deg);
    cudaGetSymbolAddress((void**)&ppool, g_pool);
    cudaGetSymbolAddress((void**)&pcnt, g_cnt);
    cudaGetSymbolAddress((void**)&pm1, g_m1);
    cudaGetSymbolAddress((void**)&pmc, g_mc);
    cudaGetSymbolAddress((void**)&pm3, g_m3);
    cudaGetSymbolAddress((void**)&pm4, g_m4);

    // degree / normalization
    k_init_deg<<<(N + 255) / 256, 256>>>(pdeg, N);
    k_count_deg<<<(E + 255) / 256, 256>>>(dstp, pdeg, E);
    k_dis<<<(N + 255) / 256, 256>>>(pdeg, pdis, N);

    auto run_layer = [&](const float* in, const float* W, const float* b,
                         int K, int M) {
        dim3 gg((M + 127) / 128, (N + 127) / 128);
        k_gemm_tc<<<gg, 256>>>(in, W, pH, N, K, M);
        size_t tot = (size_t)N * M;
        k_zero<<<(unsigned)((tot + 255) / 256), 256>>>(pA, tot);
        k_scatter<<<E, 128>>>(pH, pA, srcp, dstp, pdis, M);
        k_sbr<<<(unsigned)((tot + 255) / 256), 256>>>(pH, pA, pdis, b, N, M);
    };

    run_layer(x,  W1, b1, 1280, 1280);
    run_layer(pA, W2, b2, 1280, 640);
    run_layer(pA, W3, b3, 640, 320);

    // global mean pool
    k_zero<<<(64 * 320 + 255) / 256, 256>>>(ppool, 64 * 320);
    k_zero<<<1, 64>>>(pcnt, 64);
    k_cntk<<<(N + 255) / 256, 256>>>(batch, pcnt, N);
    {
        size_t tot = (size_t)N * 320;
        k_pool<<<(unsigned)((tot + 255) / 256), 256>>>(pA, batch, ppool, N);
    }
    k_mean<<<(64 * 320 + 255) / 256, 256>>>(ppool, pcnt);

    // MLP head
    {
        dim3 g1(1024 / 256, G);
        k_mlp<<<g1, 256>>>(ppool, Wg1, bg1, pm1, 320, 1024, 320, 1024, 0, 1);
        dim3 g2(1, G);
        k_mlp<<<g2, 128>>>(pm1, Wg2, bg2, pmc, 1024, 128, 1024, 193, 65, 0);
        k_copyfp<<<(64 * 65 + 255) / 256, 256>>>(fp_x, pmc);
        dim3 g3(1024 / 256, G);
        k_mlp<<<g3, 256>>>(pmc, Wf1, bf1, pm3, 193, 1024, 193, 1024, 0, 1);
        dim3 g4(512 / 256, G);
        k_mlp<<<g4, 256>>>(pm3, Wf2, bf2, pm4, 1024, 512, 1024, 512, 0, 1);
        k_final<<<G, 32>>>(pm4, Wo, bo, (float*)d_out);
    }
}

// round 5
// speedup vs baseline: 2.7408x; 1.6691x over previous
#include <cuda_runtime.h>
#include <cstdint>

// ===================== scratch (device globals; no allocation allowed) ======
#define MAXN 20000
#define MAXE 400000
__device__ float g_H[(size_t)MAXN * 1280];
__device__ float g_A[(size_t)MAXN * 1280];
__device__ float g_dis[MAXN];
__device__ int   g_deg[MAXN];
__device__ int   g_rowptr[MAXN + 1];
__device__ int   g_cursor[MAXN];
__device__ int   g_col[MAXE];
__device__ float g_pool[64 * 320];
__device__ float g_m1[64 * 1024];
__device__ float g_mc[64 * 193];
__device__ float g_m3[64 * 1024];
__device__ float g_m4[64 * 512];

// ===================== helpers =====================
__device__ __forceinline__ uint32_t f2tf32(float x) {
    uint32_t r;
    asm("cvt.rna.tf32.f32 %0, %1;" : "=r"(r) : "f"(x));
    return r;
}

__device__ __forceinline__ void mma_tf32(float* d, const uint32_t* a, const uint32_t* b) {
    asm volatile(
        "mma.sync.aligned.m16n8k8.row.col.f32.tf32.tf32.f32 "
        "{%0,%1,%2,%3}, {%4,%5,%6,%7}, {%8,%9}, {%0,%1,%2,%3};\n"
        : "+f"(d[0]), "+f"(d[1]), "+f"(d[2]), "+f"(d[3])
        : "r"(a[0]), "r"(a[1]), "r"(a[2]), "r"(a[3]), "r"(b[0]), "r"(b[1]));
}

// ===================== degree / normalization =====================
__global__ void k_init_deg(int* deg, int n) {
    int i = blockIdx.x * blockDim.x + threadIdx.x;
    if (i < n) deg[i] = 1;                        // self-loop
}
__global__ void k_count_deg(const int* __restrict__ dst, int* deg, int e) {
    int i = blockIdx.x * blockDim.x + threadIdx.x;
    if (i < e) atomicAdd(&deg[dst[i]], 1);
}
__global__ void k_dis(const int* __restrict__ deg, float* dis, int n) {
    int i = blockIdx.x * blockDim.x + threadIdx.x;
    if (i < n) dis[i] = rsqrtf((float)deg[i]);
}

// ===================== CSR build =====================
// single-block exclusive prefix scan of deg -> rowptr (n <= 20480)
__global__ void __launch_bounds__(1024)
k_scan(const int* __restrict__ deg, int* __restrict__ rowptr,
       int* __restrict__ cursor, int n) {
    __shared__ int sh[1024];
    const int tid = threadIdx.x;
    const int chunk = (n + 1023) / 1024;
    const int start = tid * chunk;
    const int end = (start + chunk < n) ? start + chunk : n;
    int s = 0;
    for (int i = start; i < end; i++) s += deg[i];
    sh[tid] = s;
    __syncthreads();
    // Hillis-Steele inclusive scan
    for (int off = 1; off < 1024; off <<= 1) {
        int v = (tid >= off) ? sh[tid - off] : 0;
        __syncthreads();
        sh[tid] += v;
        __syncthreads();
    }
    int run = (tid == 0) ? 0 : sh[tid - 1];
    for (int i = start; i < end; i++) {
        rowptr[i] = run;
        cursor[i] = run;
        run += deg[i];
    }
    if (start < n && end == n) rowptr[n] = run;
}

__global__ void k_fill_edges(const int* __restrict__ src, const int* __restrict__ dst,
                             int* cursor, int* __restrict__ col, int e) {
    int i = blockIdx.x * blockDim.x + threadIdx.x;
    if (i < e) {
        int pos = atomicAdd(&cursor[dst[i]], 1);
        col[pos] = src[i];
    }
}
__global__ void k_fill_self(int* cursor, int* __restrict__ col, int n) {
    int i = blockIdx.x * blockDim.x + threadIdx.x;
    if (i < n) {
        int pos = atomicAdd(&cursor[i], 1);
        col[pos] = i;
    }
}

// ===================== CSR gather: out[d] = relu(sum_j H[col[j]]*w + b) =====
// blockDim = M/5, each thread owns 5 features (stride blockDim).
__global__ void k_gather(const float* __restrict__ H, float* __restrict__ out,
                         const int* __restrict__ rowptr, const int* __restrict__ col,
                         const float* __restrict__ dis, const float* __restrict__ b,
                         int M) {
    const int d = blockIdx.x;
    const int tid = threadIdx.x;
    const int T = blockDim.x;          // M / 5
    float acc0 = 0.f, acc1 = 0.f, acc2 = 0.f, acc3 = 0.f, acc4 = 0.f;
    const float wd = dis[d];
    const int beg = rowptr[d];
    const int end = rowptr[d + 1];
    for (int j = beg; j < end; j++) {
        const int s = __ldg(&col[j]);
        const float w = __ldg(&dis[s]) * wd;
        const float* hs = H + (size_t)s * M;
        acc0 += __ldg(hs + tid) * w;
        acc1 += __ldg(hs + tid + T) * w;
        acc2 += __ldg(hs + tid + 2 * T) * w;
        acc3 += __ldg(hs + tid + 3 * T) * w;
        acc4 += __ldg(hs + tid + 4 * T) * w;
    }
    float* od = out + (size_t)d * M;
    float v;
    v = acc0 + b[tid];         od[tid]         = v > 0.f ? v : 0.f;
    v = acc1 + b[tid + T];     od[tid + T]     = v > 0.f ? v : 0.f;
    v = acc2 + b[tid + 2 * T]; od[tid + 2 * T] = v > 0.f ? v : 0.f;
    v = acc3 + b[tid + 3 * T]; od[tid + 3 * T] = v > 0.f ? v : 0.f;
    v = acc4 + b[tid + 4 * T]; od[tid + 4 * T] = v > 0.f ? v : 0.f;
}

// ===================== tensor-core tf32 GEMM ================================
// C[N, M] = A[N, K] @ W[K, M]
#define ASTRIDE 20
#define BSTRIDE 132

__global__ void __launch_bounds__(256, 2)
k_gemm_tc(const float* __restrict__ A, const float* __restrict__ W,
          float* __restrict__ C, int N, int K, int M) {
    __shared__ uint32_t As[2][128 * ASTRIDE];
    __shared__ uint32_t Bs[2][16 * BSTRIDE];

    const int tid = threadIdx.x;
    const int wid = tid >> 5;
    const int lid = tid & 31;
    const int g4  = lid >> 2;
    const int tg  = lid & 3;
    const int wm  = wid >> 2;
    const int wn  = wid & 3;
    const int row0 = blockIdx.y * 128;
    const int col0 = blockIdx.x * 128;

    float acc[4][4][4];
#pragma unroll
    for (int i = 0; i < 4; i++)
#pragma unroll
        for (int j = 0; j < 4; j++)
#pragma unroll
            for (int k = 0; k < 4; k++) acc[i][j][k] = 0.0f;

    const int ar  = tid >> 2;
    const int ac  = (tid & 3) * 4;
    const int br  = tid >> 5;
    const int bc  = (tid & 31) * 4;
    const int nk = K >> 4;

    float4 va[2], vb[2];
    auto load_tile = [&](int c) {
#pragma unroll
        for (int i = 0; i < 2; i++) {
            int r = ar + i * 64;
            int gr = row0 + r;
            va[i] = (gr < N) ? *(const float4*)(A + (size_t)gr * K + c * 16 + ac)
                             : make_float4(0.f, 0.f, 0.f, 0.f);
        }
#pragma unroll
        for (int i = 0; i < 2; i++) {
            int r = br + i * 8;
            int gc = col0 + bc;
            vb[i] = (gc < M) ? *(const float4*)(W + (size_t)(c * 16 + r) * M + gc)
                             : make_float4(0.f, 0.f, 0.f, 0.f);
        }
    };
    auto store_tile = [&](int buf) {
#pragma unroll
        for (int i = 0; i < 2; i++) {
            int r = ar + i * 64;
            uint32_t* p = &As[buf][r * ASTRIDE + ac];
            asm volatile("st.shared.v4.b32 [%0], {%1,%2,%3,%4};" ::
                "l"(p), "r"(f2tf32(va[i].x)), "r"(f2tf32(va[i].y)),
                "r"(f2tf32(va[i].z)), "r"(f2tf32(va[i].w)) : "memory");
        }
#pragma unroll
        for (int i = 0; i < 2; i++) {
            int r = br + i * 8;
            uint32_t* p = &Bs[buf][r * BSTRIDE + bc];
            asm volatile("st.shared.v4.b32 [%0], {%1,%2,%3,%4};" ::
                "l"(p), "r"(f2tf32(vb[i].x)), "r"(f2tf32(vb[i].y)),
                "r"(f2tf32(vb[i].z)), "r"(f2tf32(vb[i].w)) : "memory");
        }
    };

    load_tile(0);
    store_tile(0);
    __syncthreads();

    for (int c = 0; c < nk; c++) {
        const int buf = c & 1;
        if (c + 1 < nk) load_tile(c + 1);

        const uint32_t* __restrict__ as = As[buf];
        const uint32_t* __restrict__ bs = Bs[buf];
#pragma unroll
        for (int s = 0; s < 2; s++) {
            uint32_t af[4][4], bf[4][2];
            const int kc = s * 8;
#pragma unroll
            for (int mi = 0; mi < 4; mi++) {
                int r = wm * 64 + mi * 16 + g4;
                af[mi][0] = as[r * ASTRIDE + kc + tg];
                af[mi][1] = as[(r + 8) * ASTRIDE + kc + tg];
                af[mi][2] = as[r * ASTRIDE + kc + tg + 4];
                af[mi][3] = as[(r + 8) * ASTRIDE + kc + tg + 4];
            }
#pragma unroll
            for (int nf = 0; nf < 4; nf++) {
                int cc = wn * 32 + nf * 8 + g4;
                bf[nf][0] = bs[(kc + tg) * BSTRIDE + cc];
                bf[nf][1] = bs[(kc + tg + 4) * BSTRIDE + cc];
            }
#pragma unroll
            for (int mi = 0; mi < 4; mi++)
#pragma unroll
                for (int nf = 0; nf < 4; nf++)
                    mma_tf32(acc[mi][nf], af[mi], bf[nf]);
        }

        if (c + 1 < nk) store_tile((c + 1) & 1);
        __syncthreads();
    }

#pragma unroll
    for (int mi = 0; mi < 4; mi++) {
        int r0 = row0 + wm * 64 + mi * 16 + g4;
#pragma unroll
        for (int nf = 0; nf < 4; nf++) {
            int cc = col0 + wn * 32 + nf * 8 + tg * 2;
            if (cc < M) {
                if (r0 < N)
                    *(float2*)(C + (size_t)r0 * M + cc) =
                        make_float2(acc[mi][nf][0], acc[mi][nf][1]);
                if (r0 + 8 < N)
                    *(float2*)(C + (size_t)(r0 + 8) * M + cc) =
                        make_float2(acc[mi][nf][2], acc[mi][nf][3]);
            }
        }
    }
}

// ===================== per-graph mean pool (batch is sorted) ================
__global__ void k_pool2(const float* __restrict__ A, const int* __restrict__ batch,
                        float* __restrict__ pool, int N) {
    const int g = blockIdx.x;
    const int f = threadIdx.x;   // 320
    int lo = 0, hi = N;
    while (lo < hi) { int mid = (lo + hi) >> 1; if (batch[mid] < g) lo = mid + 1; else hi = mid; }
    const int beg = lo;
    hi = N;
    while (lo < hi) { int mid = (lo + hi) >> 1; if (batch[mid] < g + 1) lo = mid + 1; else hi = mid; }
    const int end = lo;
    float s = 0.f;
    for (int i = beg; i < end; i++) s += A[(size_t)i * 320 + f];
    pool[g * 320 + f] = s / fmaxf((float)(end - beg), 1.0f);
}

// ===================== MLP head =====================
__global__ void k_mlp(const float* __restrict__ in, const float* __restrict__ W,
                      const float* __restrict__ b, float* __restrict__ out,
                      int K, int M, int istride, int ostride, int ooff, int dorelu) {
    int g = blockIdx.y;
    int m = blockIdx.x * blockDim.x + threadIdx.x;
    if (m >= M) return;
    const float* ing = in + (size_t)g * istride;
    float acc = b[m];
    for (int k = 0; k < K; k++) acc += ing[k] * W[(size_t)k * M + m];
    if (dorelu) acc = fmaxf(acc, 0.0f);
    out[(size_t)g * ostride + ooff + m] = acc;
}

__global__ void k_copyfp(const float* __restrict__ fp, float* __restrict__ mc) {
    int idx = blockIdx.x * blockDim.x + threadIdx.x;
    if (idx < 64 * 65) {
        int g = idx / 65, j = idx % 65;
        mc[g * 193 + j] = fp[idx];
    }
}

__global__ void k_final(const float* __restrict__ in, const float* __restrict__ Wo,
                        const float* __restrict__ bo, float* __restrict__ out) {
    int g = blockIdx.x;
    float acc = 0.f;
    for (int k = threadIdx.x; k < 512; k += 32) acc += in[g * 512 + k] * Wo[k];
#pragma unroll
    for (int o = 16; o; o >>= 1) acc += __shfl_down_sync(0xFFFFFFFFu, acc, o);
    if (threadIdx.x == 0) out[g] = acc + bo[0];
}

// ===================== launch =====================
extern "C" void kernel_launch(void* const* d_in, const int* in_sizes, int n_in,
                              void* d_out, int out_size) {
    const float* x     = (const float*)d_in[0];
    const int*   ei    = (const int*)d_in[1];
    const int*   batch = (const int*)d_in[2];
    const float* fp_x  = (const float*)d_in[3];
    const float* W1 = (const float*)d_in[4];   const float* b1 = (const float*)d_in[5];
    const float* W2 = (const float*)d_in[6];   const float* b2 = (const float*)d_in[7];
    const float* W3 = (const float*)d_in[8];   const float* b3 = (const float*)d_in[9];
    const float* Wg1 = (const float*)d_in[10]; const float* bg1 = (const float*)d_in[11];
    const float* Wg2 = (const float*)d_in[12]; const float* bg2 = (const float*)d_in[13];
    const float* Wf1 = (const float*)d_in[14]; const float* bf1 = (const float*)d_in[15];
    const float* Wf2 = (const float*)d_in[16]; const float* bf2 = (const float*)d_in[17];
    const float* Wo  = (const float*)d_in[18]; const float* bo  = (const float*)d_in[19];

    const int N = in_sizes[0] / 1280;
    const int E = in_sizes[1] / 2;
    const int G = in_sizes[3] / 65;
    const int* srcp = ei;
    const int* dstp = ei + E;

    float *pH, *pA, *pdis, *ppool, *pm1, *pmc, *pm3, *pm4;
    int *pdeg, *prowptr, *pcursor, *pcol;
    cudaGetSymbolAddress((void**)&pH, g_H);
    cudaGetSymbolAddress((void**)&pA, g_A);
    cudaGetSymbolAddress((void**)&pdis, g_dis);
    cudaGetSymbolAddress((void**)&pdeg, g_deg);
    cudaGetSymbolAddress((void**)&prowptr, g_rowptr);
    cudaGetSymbolAddress((void**)&pcursor, g_cursor);
    cudaGetSymbolAddress((void**)&pcol, g_col);
    cudaGetSymbolAddress((void**)&ppool, g_pool);
    cudaGetSymbolAddress((void**)&pm1, g_m1);
    cudaGetSymbolAddress((void**)&pmc, g_mc);
    cudaGetSymbolAddress((void**)&pm3, g_m3);
    cudaGetSymbolAddress((void**)&pm4, g_m4);

    // degree / normalization / CSR
    k_init_deg<<<(N + 255) / 256, 256>>>(pdeg, N);
    k_count_deg<<<(E + 255) / 256, 256>>>(dstp, pdeg, E);
    k_dis<<<(N + 255) / 256, 256>>>(pdeg, pdis, N);
    k_scan<<<1, 1024>>>(pdeg, prowptr, pcursor, N);
    k_fill_edges<<<(E + 255) / 256, 256>>>(srcp, dstp, pcursor, pcol, E);
    k_fill_self<<<(N + 255) / 256, 256>>>(pcursor, pcol, N);

    auto run_layer = [&](const float* in, const float* W, const float* b,
                         int K, int M) {
        dim3 gg((M + 127) / 128, (N + 127) / 128);
        k_gemm_tc<<<gg, 256>>>(in, W, pH, N, K, M);
        k_gather<<<N, M / 5>>>(pH, pA, prowptr, pcol, pdis, b, M);
    };

    run_layer(x,  W1, b1, 1280, 1280);
    run_layer(pA, W2, b2, 1280, 640);
    run_layer(pA, W3, b3, 640, 320);

    // global mean pool (per-graph block, batch sorted)
    k_pool2<<<G, 320>>>(pA, batch, ppool, N);

    // MLP head
    {
        dim3 g1(1024 / 256, G);
        k_mlp<<<g1, 256>>>(ppool, Wg1, bg1, pm1, 320, 1024, 320, 1024, 0, 1);
        dim3 g2(1, G);
        k_mlp<<<g2, 128>>>(pm1, Wg2, bg2, pmc, 1024, 128, 1024, 193, 65, 0);
        k_copyfp<<<(64 * 65 + 255) / 256, 256>>>(fp_x, pmc);
        dim3 g3(1024 / 256, G);
        k_mlp<<<g3, 256>>>(pmc, Wf1, bf1, pm3, 193, 1024, 193, 1024, 0, 1);
        dim3 g4(512 / 256, G);
        k_mlp<<<g4, 256>>>(pm3, Wf2, bf2, pm4, 1024, 512, 1024, 512, 0, 1);
        k_final<<<G, 32>>>(pm4, Wo, bo, (float*)d_out);
    }
}

// round 7
// speedup vs baseline: 2.9009x; 1.0584x over previous
#include <cuda_runtime.h>
#include <cstdint>

// ===================== scratch (device globals; no allocation allowed) ======
#define MAXN 20000
#define MAXE 400000
__device__ float g_H[(size_t)MAXN * 1280];    // GEMM out (fp32, dis[row]-scaled)
__device__ float g_X[(size_t)MAXN * 1280];    // GEMM input (tf32-rounded fp32)
__device__ float g_A[(size_t)MAXN * 320];     // layer-3 gather out (fp32)
__device__ float g_WT1[1280 * 1280];
__device__ float g_WT2[640 * 1280];
__device__ float g_WT3[320 * 640];
__device__ float g_dis[MAXN];
__device__ int   g_deg[MAXN];
__device__ int   g_rowptr[MAXN + 1];
__device__ int   g_cursor[MAXN];
__device__ int   g_col[MAXE];
__device__ float g_pool[64 * 320];
__device__ float g_m1[64 * 1024];
__device__ float g_mc[64 * 193];
__device__ float g_m3[64 * 1024];
__device__ float g_m4[64 * 512];

// ===================== helpers =====================
__device__ __forceinline__ uint32_t f2tf32(float x) {
    uint32_t r;
    asm("cvt.rna.tf32.f32 %0, %1;" : "=r"(r) : "f"(x));
    return r;
}
__device__ __forceinline__ void mma_tf32(float* d, const uint32_t* a, const uint32_t* b) {
    asm volatile(
        "mma.sync.aligned.m16n8k8.row.col.f32.tf32.tf32.f32 "
        "{%0,%1,%2,%3}, {%4,%5,%6,%7}, {%8,%9}, {%0,%1,%2,%3};\n"
        : "+f"(d[0]), "+f"(d[1]), "+f"(d[2]), "+f"(d[3])
        : "r"(a[0]), "r"(a[1]), "r"(a[2]), "r"(a[3]), "r"(b[0]), "r"(b[1]));
}
__device__ __forceinline__ uint32_t smem_u32(const void* p) {
    uint32_t a;
    asm("{ .reg .u64 t; cvta.to.shared.u64 t, %1; cvt.u32.u64 %0, t; }" : "=r"(a) : "l"(p));
    return a;
}

// ===================== degree / normalization =====================
__global__ void k_init_deg(int* deg, int n) {
    int i = blockIdx.x * blockDim.x + threadIdx.x;
    if (i < n) deg[i] = 1;
}
__global__ void k_count_deg(const int* __restrict__ dst, int* deg, int e) {
    int i = blockIdx.x * blockDim.x + threadIdx.x;
    if (i < e) atomicAdd(&deg[dst[i]], 1);
}
__global__ void k_dis(const int* __restrict__ deg, float* dis, int n) {
    int i = blockIdx.x * blockDim.x + threadIdx.x;
    if (i < n) dis[i] = rsqrtf((float)deg[i]);
}

// ===================== CSR build =====================
__global__ void __launch_bounds__(1024)
k_scan(const int* __restrict__ deg, int* __restrict__ rowptr,
       int* __restrict__ cursor, int n) {
    __shared__ int sh[1024];
    const int tid = threadIdx.x;
    const int chunk = (n + 1023) / 1024;
    const int start = tid * chunk;
    const int end = (start + chunk < n) ? start + chunk : n;
    int s = 0;
    for (int i = start; i < end; i++) s += deg[i];
    sh[tid] = s;
    __syncthreads();
    for (int off = 1; off < 1024; off <<= 1) {
        int v = (tid >= off) ? sh[tid - off] : 0;
        __syncthreads();
        sh[tid] += v;
        __syncthreads();
    }
    int run = (tid == 0) ? 0 : sh[tid - 1];
    for (int i = start; i < end; i++) {
        rowptr[i] = run;
        cursor[i] = run;
        run += deg[i];
    }
    if (start < n && end == n) rowptr[n] = run;
}

__global__ void k_fill_edges(const int* __restrict__ src, const int* __restrict__ dst,
                             int* cursor, int* __restrict__ col, int e) {
    int i = blockIdx.x * blockDim.x + threadIdx.x;
    if (i < e) {
        int pos = atomicAdd(&cursor[dst[i]], 1);
        col[pos] = src[i];
    }
}
__global__ void k_fill_self(int* cursor, int* __restrict__ col, int n) {
    int i = blockIdx.x * blockDim.x + threadIdx.x;
    if (i < n) {
        int pos = atomicAdd(&cursor[i], 1);
        col[pos] = i;
    }
}

// ===================== conversions =====================
// round fp32 -> tf32 (RNA), store as fp32 bit pattern
__global__ void k_f2tf(const float* __restrict__ in, float* __restrict__ out, size_t n4) {
    size_t i = (size_t)blockIdx.x * blockDim.x + threadIdx.x;
    if (i < n4) {
        float4 v = *(const float4*)(in + i * 4);
        float4 o;
        o.x = __uint_as_float(f2tf32(v.x));
        o.y = __uint_as_float(f2tf32(v.y));
        o.z = __uint_as_float(f2tf32(v.z));
        o.w = __uint_as_float(f2tf32(v.w));
        *(float4*)(out + i * 4) = o;
    }
}

// transpose + tf32 round: WT[m][k] = tf32(W[k][m])
__global__ void k_wt(const float* __restrict__ W, float* __restrict__ WT,
                     int K, int M) {
    __shared__ float t[32][33];
    int k0 = blockIdx.y * 32, m0 = blockIdx.x * 32;
    int tx = threadIdx.x, ty = threadIdx.y;   // 32 x 8
#pragma unroll
    for (int i = ty; i < 32; i += 8)
        t[i][tx] = W[(size_t)(k0 + i) * M + m0 + tx];
    __syncthreads();
#pragma unroll
    for (int i = ty; i < 32; i += 8)
        WT[(size_t)(m0 + i) * K + k0 + tx] = __uint_as_float(f2tf32(t[tx][i]));
}

// ===================== tf32 tensor-core GEMM (cp.async, 3-stage) ============
// C[N, M] = (Atf[N, K] @ WT[M, K]^T) * dis[row]    (C fp32)
// Block tile 128x128, BK=16, 256 threads (8 warps 2x4), warp tile 64x32.
// A and B SMEM: [128 rows][20 words] (16 data + 4 pad) -> conflict-free frags.
// Stage = A(10KB) + B(10KB); 3 stages = 60KB dynamic SMEM.
#define GW 20
#define STAGE_WORDS (128 * GW * 2)

__global__ void __launch_bounds__(256, 2)
k_gemm_tf(const float* __restrict__ Atf, const float* __restrict__ WT,
          float* __restrict__ C, const float* __restrict__ dis,
          int N, int K, int M) {
    extern __shared__ uint32_t smem[];
    const uint32_t sbase0 = smem_u32(smem);
    const int tid = threadIdx.x;
    const int wid = tid >> 5;
    const int lid = tid & 31;
    const int g4  = lid >> 2;
    const int tg  = lid & 3;
    const int wm  = wid >> 2;
    const int wn  = wid & 3;
    const int row0 = blockIdx.y * 128;
    const int col0 = blockIdx.x * 128;
    const int nk = K >> 4;

    float acc[4][4][4];
#pragma unroll
    for (int i = 0; i < 4; i++)
#pragma unroll
        for (int j = 0; j < 4; j++)
#pragma unroll
            for (int k = 0; k < 4; k++) acc[i][j][k] = 0.0f;

    auto load_stage = [&](int s, int kt) {
        const int k0 = kt << 4;
        const uint32_t sb = sbase0 + (uint32_t)s * STAGE_WORDS * 4;
        // A: 128 rows x 16 floats = 512 x 16B chunks; 2 per thread
#pragma unroll
        for (int i = 0; i < 2; i++) {
            int c = tid + i * 256;
            int row = c >> 2, off = c & 3;
            int gr = row0 + row;
            int grc = gr < N ? gr : N - 1;
            const float* src = Atf + (size_t)grc * K + k0 + off * 4;
            uint32_t dst = sb + (uint32_t)(row * GW + off * 4) * 4;
            int sz = (gr < N) ? 16 : 0;
            asm volatile("cp.async.cg.shared.global [%0], [%1], 16, %2;"
                         :: "r"(dst), "l"(src), "r"(sz));
        }
        // B: 128 n-rows x 16 floats
#pragma unroll
        for (int i = 0; i < 2; i++) {
            int c = tid + i * 256;
            int n = c >> 2, off = c & 3;
            int gc = col0 + n;
            int gcc = gc < M ? gc : M - 1;
            const float* src = WT + (size_t)gcc * K + k0 + off * 4;
            uint32_t dst = sb + (uint32_t)(128 * GW + n * GW + off * 4) * 4;
            int sz = (gc < M) ? 16 : 0;
            asm volatile("cp.async.cg.shared.global [%0], [%1], 16, %2;"
                         :: "r"(dst), "l"(src), "r"(sz));
        }
        asm volatile("cp.async.commit_group;" ::: "memory");
    };

    load_stage(0, 0);
    if (nk > 1) load_stage(1, 1);

    for (int t = 0; t < nk; t++) {
        if (t + 2 <= nk)
            asm volatile("cp.async.wait_group 1;" ::: "memory");
        else
            asm volatile("cp.async.wait_group 0;" ::: "memory");
        __syncthreads();
        if (t + 2 < nk) load_stage((t + 2) % 3, t + 2);

        const uint32_t* as = smem + ((t % 3) * STAGE_WORDS);
        const uint32_t* bs = as + 128 * GW;
#pragma unroll
        for (int s = 0; s < 2; s++) {
            const int kw = s * 8;
            uint32_t af[4][4], bf[4][2];
#pragma unroll
            for (int mi = 0; mi < 4; mi++) {
                int r = wm * 64 + mi * 16 + g4;
                af[mi][0] = as[r * GW + kw + tg];
                af[mi][1] = as[(r + 8) * GW + kw + tg];
                af[mi][2] = as[r * GW + kw + tg + 4];
                af[mi][3] = as[(r + 8) * GW + kw + tg + 4];
            }
#pragma unroll
            for (int nf = 0; nf < 4; nf++) {
                int cc = wn * 32 + nf * 8 + g4;
                bf[nf][0] = bs[cc * GW + kw + tg];
                bf[nf][1] = bs[cc * GW + kw + tg + 4];
            }
#pragma unroll
            for (int mi = 0; mi < 4; mi++)
#pragma unroll
                for (int nf = 0; nf < 4; nf++)
                    mma_tf32(acc[mi][nf], af[mi], bf[nf]);
        }
    }

    // epilogue: scale rows by dis[row]
#pragma unroll
    for (int mi = 0; mi < 4; mi++) {
        int r0 = row0 + wm * 64 + mi * 16 + g4;
        float d0 = (r0 < N) ? dis[r0] : 0.f;
        float d1 = (r0 + 8 < N) ? dis[r0 + 8] : 0.f;
#pragma unroll
        for (int nf = 0; nf < 4; nf++) {
            int cc = col0 + wn * 32 + nf * 8 + tg * 2;
            if (cc < M) {
                if (r0 < N)
                    *(float2*)(C + (size_t)r0 * M + cc) =
                        make_float2(acc[mi][nf][0] * d0, acc[mi][nf][1] * d0);
                if (r0 + 8 < N)
                    *(float2*)(C + (size_t)(r0 + 8) * M + cc) =
                        make_float2(acc[mi][nf][2] * d1, acc[mi][nf][3] * d1);
            }
        }
    }
}

// ===================== CSR gather ===========================================
// out[d] = relu( (sum_j H[col[j]]) * dis[d] + b )   (H pre-scaled by dis[src])
// blockDim = M/5. tfround: round stored value to tf32 (input to next GEMM).
__global__ void k_gather(const float* __restrict__ H, float* __restrict__ out,
                         const int* __restrict__ rowptr, const int* __restrict__ col,
                         const float* __restrict__ dis, const float* __restrict__ b,
                         int M, int tfround) {
    const int d = blockIdx.x;
    const int tid = threadIdx.x;
    const int T = blockDim.x;
    float a0 = 0.f, a1 = 0.f, a2 = 0.f, a3 = 0.f, a4 = 0.f;
    const int beg = rowptr[d];
    const int end = rowptr[d + 1];
    for (int j = beg; j < end; j++) {
        const int s = __ldg(&col[j]);
        const float* hs = H + (size_t)s * M;
        a0 += __ldg(hs + tid);
        a1 += __ldg(hs + tid + T);
        a2 += __ldg(hs + tid + 2 * T);
        a3 += __ldg(hs + tid + 3 * T);
        a4 += __ldg(hs + tid + 4 * T);
    }
    const float wd = dis[d];
    float v0 = fmaxf(a0 * wd + b[tid], 0.f);
    float v1 = fmaxf(a1 * wd + b[tid + T], 0.f);
    float v2 = fmaxf(a2 * wd + b[tid + 2 * T], 0.f);
    float v3 = fmaxf(a3 * wd + b[tid + 3 * T], 0.f);
    float v4 = fmaxf(a4 * wd + b[tid + 4 * T], 0.f);
    float* od = out + (size_t)d * M;
    if (tfround) {
        od[tid]         = __uint_as_float(f2tf32(v0));
        od[tid + T]     = __uint_as_float(f2tf32(v1));
        od[tid + 2 * T] = __uint_as_float(f2tf32(v2));
        od[tid + 3 * T] = __uint_as_float(f2tf32(v3));
        od[tid + 4 * T] = __uint_as_float(f2tf32(v4));
    } else {
        od[tid]         = v0;
        od[tid + T]     = v1;
        od[tid + 2 * T] = v2;
        od[tid + 3 * T] = v3;
        od[tid + 4 * T] = v4;
    }
}

// ===================== per-graph mean pool (batch sorted) ===================
__global__ void k_pool2(const float* __restrict__ A, const int* __restrict__ batch,
                        float* __restrict__ pool, int N) {
    const int g = blockIdx.x;
    const int f = threadIdx.x;   // 320
    int lo = 0, hi = N;
    while (lo < hi) { int mid = (lo + hi) >> 1; if (batch[mid] < g) lo = mid + 1; else hi = mid; }
    const int beg = lo;
    hi = N;
    while (lo < hi) { int mid = (lo + hi) >> 1; if (batch[mid] < g + 1) lo = mid + 1; else hi = mid; }
    const int end = lo;
    float s = 0.f;
    for (int i = beg; i < end; i++) s += A[(size_t)i * 320 + f];
    pool[g * 320 + f] = s / fmaxf((float)(end - beg), 1.0f);
}

// ===================== MLP head =====================
__global__ void k_mlp(const float* __restrict__ in, const float* __restrict__ W,
                      const float* __restrict__ b, float* __restrict__ out,
                      int K, int M, int istride, int ostride, int ooff, int dorelu) {
    int g = blockIdx.y;
    int m = blockIdx.x * blockDim.x + threadIdx.x;
    if (m >= M) return;
    const float* ing = in + (size_t)g * istride;
    float acc = b[m];
    for (int k = 0; k < K; k++) acc += ing[k] * W[(size_t)k * M + m];
    if (dorelu) acc = fmaxf(acc, 0.0f);
    out[(size_t)g * ostride + ooff + m] = acc;
}

__global__ void k_copyfp(const float* __restrict__ fp, float* __restrict__ mc) {
    int idx = blockIdx.x * blockDim.x + threadIdx.x;
    if (idx < 64 * 65) {
        int g = idx / 65, j = idx % 65;
        mc[g * 193 + j] = fp[idx];
    }
}

__global__ void k_final(const float* __restrict__ in, const float* __restrict__ Wo,
                        const float* __restrict__ bo, float* __restrict__ out) {
    int g = blockIdx.x;
    float acc = 0.f;
    for (int k = threadIdx.x; k < 512; k += 32) acc += in[g * 512 + k] * Wo[k];
#pragma unroll
    for (int o = 16; o; o >>= 1) acc += __shfl_down_sync(0xFFFFFFFFu, acc, o);
    if (threadIdx.x == 0) out[g] = acc + bo[0];
}

// ===================== launch =====================
extern "C" void kernel_launch(void* const* d_in, const int* in_sizes, int n_in,
                              void* d_out, int out_size) {
    const float* x     = (const float*)d_in[0];
    const int*   ei    = (const int*)d_in[1];
    const int*   batch = (const int*)d_in[2];
    const float* fp_x  = (const float*)d_in[3];
    const float* W1 = (const float*)d_in[4];   const float* b1 = (const float*)d_in[5];
    const float* W2 = (const float*)d_in[6];   const float* b2 = (const float*)d_in[7];
    const float* W3 = (const float*)d_in[8];   const float* b3 = (const float*)d_in[9];
    const float* Wg1 = (const float*)d_in[10]; const float* bg1 = (const float*)d_in[11];
    const float* Wg2 = (const float*)d_in[12]; const float* bg2 = (const float*)d_in[13];
    const float* Wf1 = (const float*)d_in[14]; const float* bf1 = (const float*)d_in[15];
    const float* Wf2 = (const float*)d_in[16]; const float* bf2 = (const float*)d_in[17];
    const float* Wo  = (const float*)d_in[18]; const float* bo  = (const float*)d_in[19];

    const int N = in_sizes[0] / 1280;
    const int E = in_sizes[1] / 2;
    const int G = in_sizes[3] / 65;
    const int* srcp = ei;
    const int* dstp = ei + E;

    float *pH, *pX, *pA, *pdis, *ppool, *pm1, *pmc, *pm3, *pm4;
    float *pWT1, *pWT2, *pWT3;
    int *pdeg, *prowptr, *pcursor, *pcol;
    cudaGetSymbolAddress((void**)&pH, g_H);
    cudaGetSymbolAddress((void**)&pX, g_X);
    cudaGetSymbolAddress((void**)&pA, g_A);
    cudaGetSymbolAddress((void**)&pWT1, g_WT1);
    cudaGetSymbolAddress((void**)&pWT2, g_WT2);
    cudaGetSymbolAddress((void**)&pWT3, g_WT3);
    cudaGetSymbolAddress((void**)&pdis, g_dis);
    cudaGetSymbolAddress((void**)&pdeg, g_deg);
    cudaGetSymbolAddress((void**)&prowptr, g_rowptr);
    cudaGetSymbolAddress((void**)&pcursor, g_cursor);
    cudaGetSymbolAddress((void**)&pcol, g_col);
    cudaGetSymbolAddress((void**)&ppool, g_pool);
    cudaGetSymbolAddress((void**)&pm1, g_m1);
    cudaGetSymbolAddress((void**)&pmc, g_mc);
    cudaGetSymbolAddress((void**)&pm3, g_m3);
    cudaGetSymbolAddress((void**)&pm4, g_m4);

    cudaFuncSetAttribute(k_gemm_tf, cudaFuncAttributeMaxDynamicSharedMemorySize,
                         3 * STAGE_WORDS * 4);

    // degree / normalization / CSR
    k_init_deg<<<(N + 255) / 256, 256>>>(pdeg, N);
    k_count_deg<<<(E + 255) / 256, 256>>>(dstp, pdeg, E);
    k_dis<<<(N + 255) / 256, 256>>>(pdeg, pdis, N);
    k_scan<<<1, 1024>>>(pdeg, prowptr, pcursor, N);
    k_fill_edges<<<(E + 255) / 256, 256>>>(srcp, dstp, pcursor, pcol, E);
    k_fill_self<<<(N + 255) / 256, 256>>>(pcursor, pcol, N);

    // conversions: x -> tf32-rounded fp32, weights -> tf32 transposed
    {
        size_t n4 = (size_t)N * 1280 / 4;
        k_f2tf<<<(unsigned)((n4 + 255) / 256), 256>>>(x, pX, n4);
        dim3 bt(32, 8);
        k_wt<<<dim3(1280 / 32, 1280 / 32), bt>>>(W1, pWT1, 1280, 1280);
        k_wt<<<dim3(640 / 32, 1280 / 32), bt>>>(W2, pWT2, 1280, 640);
        k_wt<<<dim3(320 / 32, 640 / 32), bt>>>(W3, pWT3, 640, 320);
    }

    const unsigned smem_bytes = 3 * STAGE_WORDS * 4;
    auto gemm = [&](const float* in, const float* WT, int K, int M) {
        dim3 gg((M + 127) / 128, (N + 127) / 128);
        k_gemm_tf<<<gg, 256, smem_bytes>>>(in, WT, pH, pdis, N, K, M);
    };

    // layer 1
    gemm(pX, pWT1, 1280, 1280);
    k_gather<<<N, 256>>>(pH, pX, prowptr, pcol, pdis, b1, 1280, 1);
    // layer 2
    gemm(pX, pWT2, 1280, 640);
    k_gather<<<N, 128>>>(pH, pX, prowptr, pcol, pdis, b2, 640, 1);
    // layer 3
    gemm(pX, pWT3, 640, 320);
    k_gather<<<N, 64>>>(pH, pA, prowptr, pcol, pdis, b3, 320, 0);

    // global mean pool
    k_pool2<<<G, 320>>>(pA, batch, ppool, N);

    // MLP head
    {
        dim3 g1(1024 / 256, G);
        k_mlp<<<g1, 256>>>(ppool, Wg1, bg1, pm1, 320, 1024, 320, 1024, 0, 1);
        dim3 g2(1, G);
        k_mlp<<<g2, 128>>>(pm1, Wg2, bg2, pmc, 1024, 128, 1024, 193, 65, 0);
        k_copyfp<<<(64 * 65 + 255) / 256, 256>>>(fp_x, pmc);
        dim3 g3(1024 / 256, G);
        k_mlp<<<g3, 256>>>(pmc, Wf1, bf1, pm3, 193, 1024, 193, 1024, 0, 1);
        dim3 g4(512 / 256, G);
        k_mlp<<<g4, 256>>>(pm3, Wf2, bf2, pm4, 1024, 512, 1024, 512, 0, 1);
        k_final<<<G, 32>>>(pm4, Wo, bo, (float*)d_out);
    }
}

// round 8
// speedup vs baseline: 3.0552x; 1.0532x over previous
#include <cuda_runtime.h>
#include <cstdint>

// ===================== scratch (device globals; no allocation allowed) ======
#define MAXN 20000
#define MAXE 400000
__device__ float g_H[(size_t)MAXN * 1280];    // GEMM out (fp32, dis[row]-scaled)
__device__ float g_X[(size_t)MAXN * 1280];    // GEMM input (tf32-rounded fp32)
__device__ float g_A[(size_t)MAXN * 320];     // layer-3 gather out (fp32)
__device__ float g_WT1[1280 * 1280];
__device__ float g_WT2[640 * 1280];
__device__ float g_WT3[320 * 640];
__device__ float g_dis[MAXN];
__device__ int   g_deg[MAXN];
__device__ int   g_rowptr[MAXN + 1];
__device__ int   g_cursor[MAXN];
__device__ int   g_col[MAXE];
__device__ float g_pool[64 * 320];
__device__ float g_m1[64 * 1024];
__device__ float g_mc[64 * 193];
__device__ float g_m3[64 * 1024];
__device__ float g_m4[64 * 512];

// ===================== helpers =====================
__device__ __forceinline__ uint32_t f2tf32(float x) {
    uint32_t r;
    asm("cvt.rna.tf32.f32 %0, %1;" : "=r"(r) : "f"(x));
    return r;
}
__device__ __forceinline__ void mma_tf32(float* d, const uint32_t* a, const uint32_t* b) {
    asm volatile(
        "mma.sync.aligned.m16n8k8.row.col.f32.tf32.tf32.f32 "
        "{%0,%1,%2,%3}, {%4,%5,%6,%7}, {%8,%9}, {%0,%1,%2,%3};\n"
        : "+f"(d[0]), "+f"(d[1]), "+f"(d[2]), "+f"(d[3])
        : "r"(a[0]), "r"(a[1]), "r"(a[2]), "r"(a[3]), "r"(b[0]), "r"(b[1]));
}
__device__ __forceinline__ uint32_t smem_u32(const void* p) {
    uint32_t a;
    asm("{ .reg .u64 t; cvta.to.shared.u64 t, %1; cvt.u32.u64 %0, t; }" : "=r"(a) : "l"(p));
    return a;
}

// ===================== degree / normalization =====================
__global__ void k_init_deg(int* deg, int n) {
    int i = blockIdx.x * blockDim.x + threadIdx.x;
    if (i < n) deg[i] = 1;
}
__global__ void k_count_deg(const int* __restrict__ dst, int* deg, int e) {
    int i = blockIdx.x * blockDim.x + threadIdx.x;
    if (i < e) atomicAdd(&deg[dst[i]], 1);
}
__global__ void k_dis(const int* __restrict__ deg, float* dis, int n) {
    int i = blockIdx.x * blockDim.x + threadIdx.x;
    if (i < n) dis[i] = rsqrtf((float)deg[i]);
}

// ===================== CSR build =====================
// single-block scan, warp-shuffle based (2 barriers)
__global__ void __launch_bounds__(1024)
k_scan(const int* __restrict__ deg, int* __restrict__ rowptr,
       int* __restrict__ cursor, int n) {
    __shared__ int warpsum[32];
    const int tid = threadIdx.x;
    const int lane = tid & 31, wid = tid >> 5;
    const int chunk = (n + 1023) / 1024;
    const int start = tid * chunk;
    const int end = (start + chunk < n) ? start + chunk : n;
    int s = 0;
    for (int i = start; i < end; i++) s += deg[i];
    int v = s;
#pragma unroll
    for (int o = 1; o < 32; o <<= 1) {
        int u = __shfl_up_sync(0xFFFFFFFFu, v, o);
        if (lane >= o) v += u;
    }
    if (lane == 31) warpsum[wid] = v;
    __syncthreads();
    if (wid == 0) {
        int w = warpsum[lane];
#pragma unroll
        for (int o = 1; o < 32; o <<= 1) {
            int u = __shfl_up_sync(0xFFFFFFFFu, w, o);
            if (lane >= o) w += u;
        }
        warpsum[lane] = w;
    }
    __syncthreads();
    int incl = v + (wid ? warpsum[wid - 1] : 0);
    int run = incl - s;                 // exclusive prefix
    for (int i = start; i < end; i++) {
        rowptr[i] = run;
        cursor[i] = run;
        run += deg[i];
    }
    if (start < n && end == n) rowptr[n] = run;
}

__global__ void k_fill_edges(const int* __restrict__ src, const int* __restrict__ dst,
                             int* cursor, int* __restrict__ col, int e) {
    int i = blockIdx.x * blockDim.x + threadIdx.x;
    if (i < e) {
        int pos = atomicAdd(&cursor[dst[i]], 1);
        col[pos] = src[i];
    }
}
__global__ void k_fill_self(int* cursor, int* __restrict__ col, int n) {
    int i = blockIdx.x * blockDim.x + threadIdx.x;
    if (i < n) {
        int pos = atomicAdd(&cursor[i], 1);
        col[pos] = i;
    }
}

// ===================== conversions =====================
__global__ void k_f2tf(const float* __restrict__ in, float* __restrict__ out, size_t n4) {
    size_t i = (size_t)blockIdx.x * blockDim.x + threadIdx.x;
    if (i < n4) {
        float4 v = *(const float4*)(in + i * 4);
        float4 o;
        o.x = __uint_as_float(f2tf32(v.x));
        o.y = __uint_as_float(f2tf32(v.y));
        o.z = __uint_as_float(f2tf32(v.z));
        o.w = __uint_as_float(f2tf32(v.w));
        *(float4*)(out + i * 4) = o;
    }
}

__global__ void k_wt(const float* __restrict__ W, float* __restrict__ WT,
                     int K, int M) {
    __shared__ float t[32][33];
    int k0 = blockIdx.y * 32, m0 = blockIdx.x * 32;
    int tx = threadIdx.x, ty = threadIdx.y;   // 32 x 8
#pragma unroll
    for (int i = ty; i < 32; i += 8)
        t[i][tx] = W[(size_t)(k0 + i) * M + m0 + tx];
    __syncthreads();
#pragma unroll
    for (int i = ty; i < 32; i += 8)
        WT[(size_t)(m0 + i) * K + k0 + tx] = __uint_as_float(f2tf32(t[tx][i]));
}

// ===================== tf32 tensor-core GEMM (cp.async, 4-stage) ============
// C[N, M] = (Atf[N, K] @ WT[M, K]^T) * dis[row]    (C fp32)
// Block tile 128x128, BK=16, 256 threads (8 warps 2x4), warp tile 64x32.
#define GW 20
#define STAGE_WORDS (128 * GW * 2)
#define NSTAGE 4

__global__ void __launch_bounds__(256, 2)
k_gemm_tf(const float* __restrict__ Atf, const float* __restrict__ WT,
          float* __restrict__ C, const float* __restrict__ dis,
          int N, int K, int M) {
    extern __shared__ uint32_t smem[];
    const uint32_t sbase0 = smem_u32(smem);
    const int tid = threadIdx.x;
    const int wid = tid >> 5;
    const int lid = tid & 31;
    const int g4  = lid >> 2;
    const int tg  = lid & 3;
    const int wm  = wid >> 2;
    const int wn  = wid & 3;
    const int row0 = blockIdx.y * 128;
    const int col0 = blockIdx.x * 128;
    const int nk = K >> 4;

    float acc[4][4][4];
#pragma unroll
    for (int i = 0; i < 4; i++)
#pragma unroll
        for (int j = 0; j < 4; j++)
#pragma unroll
            for (int k = 0; k < 4; k++) acc[i][j][k] = 0.0f;

    auto load_stage = [&](int s, int kt) {
        const int k0 = kt << 4;
        const uint32_t sb = sbase0 + (uint32_t)s * STAGE_WORDS * 4;
#pragma unroll
        for (int i = 0; i < 2; i++) {
            int c = tid + i * 256;
            int row = c >> 2, off = c & 3;
            int gr = row0 + row;
            int grc = gr < N ? gr : N - 1;
            const float* src = Atf + (size_t)grc * K + k0 + off * 4;
            uint32_t dst = sb + (uint32_t)(row * GW + off * 4) * 4;
            int sz = (gr < N) ? 16 : 0;
            asm volatile("cp.async.cg.shared.global [%0], [%1], 16, %2;"
                         :: "r"(dst), "l"(src), "r"(sz));
        }
#pragma unroll
        for (int i = 0; i < 2; i++) {
            int c = tid + i * 256;
            int n = c >> 2, off = c & 3;
            int gc = col0 + n;
            int gcc = gc < M ? gc : M - 1;
            const float* src = WT + (size_t)gcc * K + k0 + off * 4;
            uint32_t dst = sb + (uint32_t)(128 * GW + n * GW + off * 4) * 4;
            int sz = (gc < M) ? 16 : 0;
            asm volatile("cp.async.cg.shared.global [%0], [%1], 16, %2;"
                         :: "r"(dst), "l"(src), "r"(sz));
        }
        asm volatile("cp.async.commit_group;" ::: "memory");
    };

    for (int s = 0; s < NSTAGE - 1 && s < nk; s++) load_stage(s, s);

    for (int t = 0; t < nk; t++) {
        if (t + NSTAGE - 1 <= nk)
            asm volatile("cp.async.wait_group %0;" :: "n"(NSTAGE - 2) : "memory");
        else
            asm volatile("cp.async.wait_group 0;" ::: "memory");
        __syncthreads();
        if (t + NSTAGE - 1 < nk) load_stage((t + NSTAGE - 1) % NSTAGE, t + NSTAGE - 1);

        const uint32_t* as = smem + ((t % NSTAGE) * STAGE_WORDS);
        const uint32_t* bs = as + 128 * GW;
#pragma unroll
        for (int s = 0; s < 2; s++) {
            const int kw = s * 8;
            uint32_t af[4][4], bf[4][2];
#pragma unroll
            for (int mi = 0; mi < 4; mi++) {
                int r = wm * 64 + mi * 16 + g4;
                af[mi][0] = as[r * GW + kw + tg];
                af[mi][1] = as[(r + 8) * GW + kw + tg];
                af[mi][2] = as[r * GW + kw + tg + 4];
                af[mi][3] = as[(r + 8) * GW + kw + tg + 4];
            }
#pragma unroll
            for (int nf = 0; nf < 4; nf++) {
                int cc = wn * 32 + nf * 8 + g4;
                bf[nf][0] = bs[cc * GW + kw + tg];
                bf[nf][1] = bs[cc * GW + kw + tg + 4];
            }
#pragma unroll
            for (int mi = 0; mi < 4; mi++)
#pragma unroll
                for (int nf = 0; nf < 4; nf++)
                    mma_tf32(acc[mi][nf], af[mi], bf[nf]);
        }
    }

#pragma unroll
    for (int mi = 0; mi < 4; mi++) {
        int r0 = row0 + wm * 64 + mi * 16 + g4;
        float d0 = (r0 < N) ? dis[r0] : 0.f;
        float d1 = (r0 + 8 < N) ? dis[r0 + 8] : 0.f;
#pragma unroll
        for (int nf = 0; nf < 4; nf++) {
            int cc = col0 + wn * 32 + nf * 8 + tg * 2;
            if (cc < M) {
                if (r0 < N)
                    *(float2*)(C + (size_t)r0 * M + cc) =
                        make_float2(acc[mi][nf][0] * d0, acc[mi][nf][1] * d0);
                if (r0 + 8 < N)
                    *(float2*)(C + (size_t)(r0 + 8) * M + cc) =
                        make_float2(acc[mi][nf][2] * d1, acc[mi][nf][3] * d1);
            }
        }
    }
}

// ===================== CSR gather (float4, edge-unrolled) ====================
// out[d, fo + 4t] = relu( (sum_j H[col[j], fo+4t]) * dis[d] + b[fo+4t] )
// H rows pre-scaled by dis[src] in GEMM epilogue. blockDim = Mw/4.
__global__ void k_gather4(const float* __restrict__ H, float* __restrict__ out,
                          const int* __restrict__ rowptr, const int* __restrict__ col,
                          const float* __restrict__ dis, const float* __restrict__ b,
                          int M, int fo, int tfround) {
    const int d = blockIdx.x;
    const int t = threadIdx.x;
    float4 acc = make_float4(0.f, 0.f, 0.f, 0.f);
    const int beg = rowptr[d];
    const int end = rowptr[d + 1];
    int j = beg;
    for (; j + 1 < end; j += 2) {
        const int s0 = __ldg(&col[j]);
        const int s1 = __ldg(&col[j + 1]);
        float4 v0 = __ldg((const float4*)(H + (size_t)s0 * M + fo) + t);
        float4 v1 = __ldg((const float4*)(H + (size_t)s1 * M + fo) + t);
        acc.x += v0.x + v1.x;
        acc.y += v0.y + v1.y;
        acc.z += v0.z + v1.z;
        acc.w += v0.w + v1.w;
    }
    if (j < end) {
        const int s0 = __ldg(&col[j]);
        float4 v0 = __ldg((const float4*)(H + (size_t)s0 * M + fo) + t);
        acc.x += v0.x; acc.y += v0.y; acc.z += v0.z; acc.w += v0.w;
    }
    const float wd = dis[d];
    float4 bb = __ldg((const float4*)(b + fo) + t);
    float4 r;
    r.x = fmaxf(acc.x * wd + bb.x, 0.f);
    r.y = fmaxf(acc.y * wd + bb.y, 0.f);
    r.z = fmaxf(acc.z * wd + bb.z, 0.f);
    r.w = fmaxf(acc.w * wd + bb.w, 0.f);
    if (tfround) {
        r.x = __uint_as_float(f2tf32(r.x));
        r.y = __uint_as_float(f2tf32(r.y));
        r.z = __uint_as_float(f2tf32(r.z));
        r.w = __uint_as_float(f2tf32(r.w));
    }
    ((float4*)(out + (size_t)d * M + fo))[t] = r;
}

// ===================== per-graph mean pool (batch sorted) ===================
__global__ void k_pool2(const float* __restrict__ A, const int* __restrict__ batch,
                        float* __restrict__ pool, int N) {
    const int g = blockIdx.x;
    const int f = threadIdx.x;   // 320
    int lo = 0, hi = N;
    while (lo < hi) { int mid = (lo + hi) >> 1; if (batch[mid] < g) lo = mid + 1; else hi = mid; }
    const int beg = lo;
    hi = N;
    while (lo < hi) { int mid = (lo + hi) >> 1; if (batch[mid] < g + 1) lo = mid + 1; else hi = mid; }
    const int end = lo;
    float s = 0.f;
    for (int i = beg; i < end; i++) s += A[(size_t)i * 320 + f];
    pool[g * 320 + f] = s / fmaxf((float)(end - beg), 1.0f);
}

// ===================== MLP head =====================
__global__ void k_mlp(const float* __restrict__ in, const float* __restrict__ W,
                      const float* __restrict__ b, float* __restrict__ out,
                      int K, int M, int istride, int ostride, int ooff, int dorelu) {
    int g = blockIdx.y;
    int m = blockIdx.x * blockDim.x + threadIdx.x;
    if (m >= M) return;
    const float* ing = in + (size_t)g * istride;
    float acc = b[m];
    for (int k = 0; k < K; k++) acc += ing[k] * W[(size_t)k * M + m];
    if (dorelu) acc = fmaxf(acc, 0.0f);
    out[(size_t)g * ostride + ooff + m] = acc;
}

__global__ void k_copyfp(const float* __restrict__ fp, float* __restrict__ mc) {
    int idx = blockIdx.x * blockDim.x + threadIdx.x;
    if (idx < 64 * 65) {
        int g = idx / 65, j = idx % 65;
        mc[g * 193 + j] = fp[idx];
    }
}

__global__ void k_final(const float* __restrict__ in, const float* __restrict__ Wo,
                        const float* __restrict__ bo, float* __restrict__ out) {
    int g = blockIdx.x;
    float acc = 0.f;
    for (int k = threadIdx.x; k < 512; k += 32) acc += in[g * 512 + k] * Wo[k];
#pragma unroll
    for (int o = 16; o; o >>= 1) acc += __shfl_down_sync(0xFFFFFFFFu, acc, o);
    if (threadIdx.x == 0) out[g] = acc + bo[0];
}

// ===================== launch =====================
extern "C" void kernel_launch(void* const* d_in, const int* in_sizes, int n_in,
                              void* d_out, int out_size) {
    const float* x     = (const float*)d_in[0];
    const int*   ei    = (const int*)d_in[1];
    const int*   batch = (const int*)d_in[2];
    const float* fp_x  = (const float*)d_in[3];
    const float* W1 = (const float*)d_in[4];   const float* b1 = (const float*)d_in[5];
    const float* W2 = (const float*)d_in[6];   const float* b2 = (const float*)d_in[7];
    const float* W3 = (const float*)d_in[8];   const float* b3 = (const float*)d_in[9];
    const float* Wg1 = (const float*)d_in[10]; const float* bg1 = (const float*)d_in[11];
    const float* Wg2 = (const float*)d_in[12]; const float* bg2 = (const float*)d_in[13];
    const float* Wf1 = (const float*)d_in[14]; const float* bf1 = (const float*)d_in[15];
    const float* Wf2 = (const float*)d_in[16]; const float* bf2 = (const float*)d_in[17];
    const float* Wo  = (const float*)d_in[18]; const float* bo  = (const float*)d_in[19];

    const int N = in_sizes[0] / 1280;
    const int E = in_sizes[1] / 2;
    const int G = in_sizes[3] / 65;
    const int* srcp = ei;
    const int* dstp = ei + E;

    float *pH, *pX, *pA, *pdis, *ppool, *pm1, *pmc, *pm3, *pm4;
    float *pWT1, *pWT2, *pWT3;
    int *pdeg, *prowptr, *pcursor, *pcol;
    cudaGetSymbolAddress((void**)&pH, g_H);
    cudaGetSymbolAddress((void**)&pX, g_X);
    cudaGetSymbolAddress((void**)&pA, g_A);
    cudaGetSymbolAddress((void**)&pWT1, g_WT1);
    cudaGetSymbolAddress((void**)&pWT2, g_WT2);
    cudaGetSymbolAddress((void**)&pWT3, g_WT3);
    cudaGetSymbolAddress((void**)&pdis, g_dis);
    cudaGetSymbolAddress((void**)&pdeg, g_deg);
    cudaGetSymbolAddress((void**)&prowptr, g_rowptr);
    cudaGetSymbolAddress((void**)&pcursor, g_cursor);
    cudaGetSymbolAddress((void**)&pcol, g_col);
    cudaGetSymbolAddress((void**)&ppool, g_pool);
    cudaGetSymbolAddress((void**)&pm1, g_m1);
    cudaGetSymbolAddress((void**)&pmc, g_mc);
    cudaGetSymbolAddress((void**)&pm3, g_m3);
    cudaGetSymbolAddress((void**)&pm4, g_m4);

    cudaFuncSetAttribute(k_gemm_tf, cudaFuncAttributeMaxDynamicSharedMemorySize,
                         NSTAGE * STAGE_WORDS * 4);

    // degree / normalization / CSR
    k_init_deg<<<(N + 255) / 256, 256>>>(pdeg, N);
    k_count_deg<<<(E + 255) / 256, 256>>>(dstp, pdeg, E);
    k_dis<<<(N + 255) / 256, 256>>>(pdeg, pdis, N);
    k_scan<<<1, 1024>>>(pdeg, prowptr, pcursor, N);
    k_fill_edges<<<(E + 255) / 256, 256>>>(srcp, dstp, pcursor, pcol, E);
    k_fill_self<<<(N + 255) / 256, 256>>>(pcursor, pcol, N);

    // conversions: x -> tf32-rounded fp32, weights -> tf32 transposed
    {
        size_t n4 = (size_t)N * 1280 / 4;
        k_f2tf<<<(unsigned)((n4 + 255) / 256), 256>>>(x, pX, n4);
        dim3 bt(32, 8);
        k_wt<<<dim3(1280 / 32, 1280 / 32), bt>>>(W1, pWT1, 1280, 1280);
        k_wt<<<dim3(640 / 32, 1280 / 32), bt>>>(W2, pWT2, 1280, 640);
        k_wt<<<dim3(320 / 32, 640 / 32), bt>>>(W3, pWT3, 640, 320);
    }

    const unsigned smem_bytes = NSTAGE * STAGE_WORDS * 4;
    auto gemm = [&](const float* in, const float* WT, int K, int M) {
        dim3 gg((M + 127) / 128, (N + 127) / 128);
        k_gemm_tf<<<gg, 256, smem_bytes>>>(in, WT, pH, pdis, N, K, M);
    };

    // layer 1 (gather in two 640-feature passes to keep H-half L2-resident)
    gemm(pX, pWT1, 1280, 1280);
    k_gather4<<<N, 160>>>(pH, pX, prowptr, pcol, pdis, b1, 1280, 0,   1);
    k_gather4<<<N, 160>>>(pH, pX, prowptr, pcol, pdis, b1, 1280, 640, 1);
    // layer 2
    gemm(pX, pWT2, 1280, 640);
    k_gather4<<<N, 160>>>(pH, pX, prowptr, pcol, pdis, b2, 640, 0, 1);
    // layer 3
    gemm(pX, pWT3, 640, 320);
    k_gather4<<<N, 80>>>(pH, pA, prowptr, pcol, pdis, b3, 320, 0, 0);

    // global mean pool
    k_pool2<<<G, 320>>>(pA, batch, ppool, N);

    // MLP head
    {
        dim3 g1(1024 / 256, G);
        k_mlp<<<g1, 256>>>(ppool, Wg1, bg1, pm1, 320, 1024, 320, 1024, 0, 1);
        dim3 g2(1, G);
        k_mlp<<<g2, 128>>>(pm1, Wg2, bg2, pmc, 1024, 128, 1024, 193, 65, 0);
        k_copyfp<<<(64 * 65 + 255) / 256, 256>>>(fp_x, pmc);
        dim3 g3(1024 / 256, G);
        k_mlp<<<g3, 256>>>(pmc, Wf1, bf1, pm3, 193, 1024, 193, 1024, 0, 1);
        dim3 g4(512 / 256, G);
        k_mlp<<<g4, 256>>>(pm3, Wf2, bf2, pm4, 1024, 512, 1024, 512, 0, 1);
        k_final<<<G, 32>>>(pm4, Wo, bo, (float*)d_out);
    }
}